// round 7
// baseline (speedup 1.0000x reference)
#include <cuda_runtime.h>
#include <math.h>

#define SUBNETS 64
#define NH1 10
#define NH2 6
#define GRIDN 101
#define K_INT 52             // intervals (delta = 1/4)
#define KNOTS 53             // knots = K_INT + 1
#define TAB_LO  (-6.5f)
#define TAB_DX  (0.25f)      // 1/4
#define TAB_INVDX (4.0f)
#define TAB_BIAS  (26.0f)    // 6.5 * 4

#define EVAL_BLOCK 512
#define EVAL_BPSM  3
#define EVAL_GRID  (148 * EVAL_BPSM)                        // 444
#define SMEM_BYTES (SUBNETS * K_INT * (int)sizeof(float4))  // 53,248 B

// Piecewise-cubic table, INTERVAL-MAJOR: g_table[j*64 + s] = (c0,c1,c2,c3)
// for subnet s, interval j. Conflict-free warp LDS.128 gathers: within an
// 8-lane phase, bank-quad = (j*64+s) mod 8 = s mod 8, and s = tid & 63 is
// 8 consecutive values per phase.
__device__ float4 g_table[K_INT * SUBNETS];

// Accurate MLP evaluation (value + analytic derivative) for one subnet.
__device__ __forceinline__ void mlp_eval(
    float x, int s,
    const float* __restrict__ W1, const float* __restrict__ b1,
    const float* __restrict__ W2, const float* __restrict__ b2,
    const float* __restrict__ W3, const float* __restrict__ b3,
    float* f_out, float* d_out)
{
    float h1[NH1], dh1[NH1];
#pragma unroll
    for (int h = 0; h < NH1; h++) {
        float w = W1[s * NH1 + h];
        float p = fmaf(w, x, b1[s * NH1 + h]);
        float t = tanhf(p);
        h1[h]  = t;
        dh1[h] = (1.0f - t * t) * w;
    }
    float f = b3[s];
    float d = 0.0f;
#pragma unroll
    for (int k = 0; k < NH2; k++) {
        float a  = b2[s * NH2 + k];
        float da = 0.0f;
#pragma unroll
        for (int h = 0; h < NH1; h++) {
            float w2 = W2[(s * NH1 + h) * NH2 + k];
            a  = fmaf(h1[h],  w2, a);
            da = fmaf(dh1[h], w2, da);
        }
        float t  = tanhf(a);
        float w3 = W3[s * NH2 + k];
        f = fmaf(t, w3, f);
        d = fmaf((1.0f - t * t) * da, w3, d);
    }
    *f_out = f;
    *d_out = d;
}

// One block per subnet: grid stats (parallel double reduction) + Hermite
// coefficients with normalization folded in; writes transposed table.
__global__ __launch_bounds__(256)
void setup_kernel(const float* __restrict__ W1, const float* __restrict__ b1,
                  const float* __restrict__ W2, const float* __restrict__ b2,
                  const float* __restrict__ W3, const float* __restrict__ b3)
{
    __shared__ float sh_g[GRIDN];
    __shared__ float sh_f[KNOTS];
    __shared__ float sh_d[KNOTS];
    __shared__ float sh_mean, sh_inv;

    const int s = blockIdx.x;
    const int t = threadIdx.x;

    if (t < GRIDN) {
        float x = fmaf((float)t, 0.02f, -1.0f);   // linspace(-1,1,101)
        float f, d;
        mlp_eval(x, s, W1, b1, W2, b2, W3, b3, &f, &d);
        sh_g[t] = f;
    }
    if (t < KNOTS) {
        float x = fmaf((float)t, TAB_DX, TAB_LO);
        float f, d;
        mlp_eval(x, s, W1, b1, W2, b2, W3, b3, &f, &d);
        sh_f[t] = f;
        sh_d[t] = d;
    }
    __syncthreads();

    // Warp 0: parallel double-precision sum / sumsq over the 101 grid values.
    if (t < 32) {
        double m = 0.0, m2 = 0.0;
        for (int i = t; i < GRIDN; i += 32) {
            double g = (double)sh_g[i];
            m  += g;
            m2 += g * g;
        }
#pragma unroll
        for (int o = 16; o > 0; o >>= 1) {
            m  += __shfl_down_sync(0xFFFFFFFFu, m,  o);
            m2 += __shfl_down_sync(0xFFFFFFFFu, m2, o);
        }
        if (t == 0) {
            m  /= (double)GRIDN;
            m2 /= (double)GRIDN;
            double var = m2 - m * m;
            if (var < 0.0) var = 0.0;
            double sd = sqrt(var);
            if (sd < 1e-10) sd = 1e-10;
            sh_mean = (float)m;
            sh_inv  = (float)(1.0 / sd);
        }
    }
    __syncthreads();

    if (t < K_INT) {
        const float mean = sh_mean;
        const float inv  = sh_inv;
        float f0 = (sh_f[t]     - mean) * inv;
        float f1 = (sh_f[t + 1] - mean) * inv;
        float m0 = sh_d[t]     * inv * TAB_DX;
        float m1 = sh_d[t + 1] * inv * TAB_DX;
        float c2 = 3.0f * (f1 - f0) - 2.0f * m0 - m1;
        float c3 = 2.0f * (f0 - f1) + m0 + m1;
        g_table[t * SUBNETS + s] = make_float4(f0, m0, c2, c3);  // transposed
    }
}

__device__ __forceinline__ float cubic_lookup(const float4* __restrict__ tab,
                                              int s, float x)
{
    float q  = fmaf(x, TAB_INVDX, TAB_BIAS);   // (x + 6.5) * 4
    float jf = floorf(q);
    jf = fminf(fmaxf(jf, 0.0f), (float)(K_INT - 1));
    float tt = q - jf;
    float4 c = tab[(int)jf * SUBNETS + s];
    return fmaf(fmaf(fmaf(c.w, tt, c.z), tt, c.y), tt, c.x);
}

// Main kernel: one subnet per thread (s = tid & 63), coalesced LDG.32/STG.32,
// conflict-free LDS.128 table gathers, software-pipelined unroll x4:
// iteration n+1's global loads are issued before iteration n's values are
// consumed, hiding the ~400-600 cyc LDG latency behind LDS+FFMA+STG work.
// 512 threads x 3 blocks/SM: 48 warps with a 42-register budget.
__global__ __launch_bounds__(EVAL_BLOCK, EVAL_BPSM)
void eval_kernel(const float* __restrict__ in, const int* __restrict__ idx,
                 float* __restrict__ out, int n)
{
    extern __shared__ float4 tab[];          // [K_INT][SUBNETS]

    for (int i = threadIdx.x; i < K_INT * SUBNETS; i += EVAL_BLOCK)
        tab[i] = g_table[i];
    __syncthreads();

    const int tid      = blockIdx.x * EVAL_BLOCK + threadIdx.x;
    const int nthreads = EVAL_GRID * EVAL_BLOCK;     // multiple of 64

    const int s   = tid & 63;
    const int off = idx[s] - s;   // in[b*64 + idx[s]] == in[i + off]
    const float* __restrict__ inp = in + off;

    const int stride = nthreads;
    const int step   = 4 * stride;

    int i = tid;
    float x0, x1, x2, x3;
    bool have = (i + 3 * stride < n);
    if (have) {
        x0 = __ldg(inp + i);
        x1 = __ldg(inp + i + stride);
        x2 = __ldg(inp + i + 2 * stride);
        x3 = __ldg(inp + i + 3 * stride);
    }

    while (have) {
        const int ni = i + step;
        const bool nhave = (ni + 3 * stride < n);
        float y0, y1, y2, y3;
        if (nhave) {                          // prefetch next quad first
            y0 = __ldg(inp + ni);
            y1 = __ldg(inp + ni + stride);
            y2 = __ldg(inp + ni + 2 * stride);
            y3 = __ldg(inp + ni + 3 * stride);
        }

        float r0 = cubic_lookup(tab, s, x0);
        float r1 = cubic_lookup(tab, s, x1);
        float r2 = cubic_lookup(tab, s, x2);
        float r3 = cubic_lookup(tab, s, x3);
        out[i]              = r0;
        out[i +     stride] = r1;
        out[i + 2 * stride] = r2;
        out[i + 3 * stride] = r3;

        i = ni;
        x0 = y0; x1 = y1; x2 = y2; x3 = y3;
        have = nhave;
    }

    for (; i < n; i += stride) {             // tail (< 4 elems per thread)
        float x = __ldg(inp + i);
        out[i] = cubic_lookup(tab, s, x);
    }
}

extern "C" void kernel_launch(void* const* d_in, const int* in_sizes, int n_in,
                              void* d_out, int out_size)
{
    const float* inputs = (const float*)d_in[0];
    const int*   idx    = (const int*)  d_in[1];
    const float* W1     = (const float*)d_in[2];
    const float* b1     = (const float*)d_in[3];
    const float* W2     = (const float*)d_in[4];
    const float* b2     = (const float*)d_in[5];
    const float* W3     = (const float*)d_in[6];
    const float* b3     = (const float*)d_in[7];
    float*       outp   = (float*)d_out;

    cudaFuncSetAttribute(eval_kernel,
                         cudaFuncAttributeMaxDynamicSharedMemorySize,
                         SMEM_BYTES);

    setup_kernel<<<SUBNETS, 256>>>(W1, b1, W2, b2, W3, b3);

    eval_kernel<<<EVAL_GRID, EVAL_BLOCK, SMEM_BYTES>>>(inputs, idx, outp,
                                                       out_size);
}